// round 12
// baseline (speedup 1.0000x reference)
#include <cuda_runtime.h>
#include <stdint.h>

static const int kC = 256, kHW = 65536, kBins = 256;
static const int kB = 8192;                // value buckets (top-13 key bits)
static const int kSegs = 768;
static const int kT = 1024;                // threads per CTA (max warps/SM)
static const unsigned int kSent = 0xFFFFFFFFu;

__device__ double       g_pS1[kSegs];
__device__ double       g_pS2[kSegs];
__device__ unsigned int g_Mc[kC];
__device__ unsigned int g_done;            // zero at load; reset by last block

__device__ __forceinline__ unsigned int key_xform(float f) {
    unsigned int u = __float_as_uint(f);
    return (u & 0x80000000u) ? ~u : (u | 0x80000000u);
}

// f32 quantile target: t_r = ((float)r * 2^-16) * total  (monotone in r)
__device__ __forceinline__ float t_of(int r, float total) {
    return ((float)r * 0x1p-16f) * total;
}

#define CP_ASYNC16(dst, src) \
    asm volatile("cp.async.cg.shared.global [%0], [%1], 16;" :: "r"(dst), "l"(src))
#define CP_COMMIT() asm volatile("cp.async.commit_group;")
#define CP_WAIT1()  asm volatile("cp.async.wait_group 1;")

__global__ void __launch_bounds__(kT, 2) fused_kernel(
    const float* __restrict__ o0, const float* __restrict__ o1, const float* __restrict__ o2,
    const float* __restrict__ h0, const float* __restrict__ h1, const float* __restrict__ h2,
    const float* __restrict__ mn0, const float* __restrict__ mn1, const float* __restrict__ mn2,
    const float* __restrict__ mx0, const float* __restrict__ mx1, const float* __restrict__ mx2,
    const int* __restrict__ mask, const float* __restrict__ w, float* __restrict__ out) {
    extern __shared__ unsigned int dyn[];
    unsigned int* H = dyn;                 // packed: tot | masked<<16
    unsigned int* T = dyn + kB;            // scan of totals (= staging buf0 earlier)
    unsigned int* M = dyn + 2 * kB;        // scan of masked (= staging buf1 earlier)
    __shared__ float        cdf[256];
    __shared__ unsigned int s1arr[256];    // boundary ranks (kSent = no contribution)
    __shared__ float        swf[32];
    __shared__ unsigned int swu[32], swu2[32];
    __shared__ double       swd[32];
    __shared__ unsigned int sMc, sticket;
    __shared__ float        sTotal;

    int bid = blockIdx.x;
    int c = bid / 3, l = bid % 3;          // 3 levels of a channel adjacent -> mask L2 reuse
    const float* opt = (l == 0) ? o0 : (l == 1) ? o1 : o2;
    int tid = threadIdx.x, lane = tid & 31, warp = tid >> 5;

    for (int i = tid; i < kB; i += kT) H[i] = 0u;

    // ---- parallel target-CDF build (warp 0): 8 bins/lane + shuffle scan ----
    const float* hist = ((l == 0) ? h0 : (l == 1) ? h1 : h2) + (size_t)c * kBins;
    if (warp == 0) {
        const float4* hv = reinterpret_cast<const float4*>(hist);
        float4 a = hv[lane * 2], b = hv[lane * 2 + 1];
        float v[8] = {a.x, a.y, a.z, a.w, b.x, b.y, b.z, b.w};
        float run = 0.f, pref[8];
#pragma unroll
        for (int i = 0; i < 8; i++) { run += v[i]; pref[i] = run; }
        float incl = run;
#pragma unroll
        for (int off = 1; off < 32; off <<= 1) {
            float o = __shfl_up_sync(0xFFFFFFFFu, incl, off);
            if (lane >= off) incl += o;
        }
        float excl = incl - run;
#pragma unroll
        for (int i = 0; i < 8; i++) cdf[lane * 8 + i] = excl + pref[i];
        if (lane == 31) sTotal = incl;
    }
    __syncthreads();   // H zeroed, cdf + sTotal ready

    // ---- boundary ranks (overlaps with histogram start on other warps) ----
    if (tid < 255) {
        float cj = cdf[tid], total = sTotal;
        unsigned int s1 = kSent;
        if (t_of(65536, total) > cj) {
            int lo = 1, hi = 65536;                  // min r with t_r > cj
            while (lo < hi) { int mid = (lo + hi) >> 1;
                              if (t_of(mid, total) > cj) hi = mid; else lo = mid + 1; }
            s1 = (unsigned int)(lo - 1);
        }
        s1arr[tid] = s1;
    }

    // ---- Phase A: compress 64 mask bits/thread into 2 regs (deep LDG batch) ----
    const float4* ov = reinterpret_cast<const float4*>(opt) + (size_t)c * (kHW / 4);
    const int4*   mv = reinterpret_cast<const int4*>(mask)  + (size_t)c * (kHW / 4);
    unsigned int mb0 = 0u, mb1 = 0u;
#pragma unroll
    for (int i = 0; i < 8; i++) {
        int4 m = mv[tid + kT * i];
        unsigned int b = (m.x ? 1u : 0u) | (m.y ? 2u : 0u) | (m.z ? 4u : 0u) | (m.w ? 8u : 0u);
        mb0 |= b << (i * 4);
    }
#pragma unroll
    for (int i = 0; i < 8; i++) {
        int4 m = mv[tid + kT * (8 + i)];
        unsigned int b = (m.x ? 1u : 0u) | (m.y ? 2u : 0u) | (m.z ? 4u : 0u) | (m.w ? 8u : 0u);
        mb1 |= b << (i * 4);
    }

    // ---- Phase B: cp.async double-buffered staging (T/M regions as buffers) ----
    // 8 chunks of 2048 float4 (2 per thread). Each thread stages and consumes
    // its own 16B slots -> per-thread wait_group, no block sync needed.
    float fsum = 0.f;
#pragma unroll
    for (int cch = 0; cch < 2; cch++) {    // preload chunks 0,1
#pragma unroll
        for (int j = 0; j < 2; j++) {
            unsigned int dst = (unsigned int)__cvta_generic_to_shared(
                &dyn[kB * (1 + (cch & 1)) + (j * kT + tid) * 4]);
            CP_ASYNC16(dst, &ov[cch * 2048 + j * kT + tid]);
        }
        CP_COMMIT();
    }
#pragma unroll
    for (int cch = 0; cch < 8; cch++) {
        CP_WAIT1();                        // chunk cch arrived (<=1 group pending after)
        float4* buf = reinterpret_cast<float4*>(&dyn[kB * (1 + (cch & 1))]);
#pragma unroll
        for (int j = 0; j < 2; j++) {
            float4 v = buf[j * kT + tid];
            int i = cch * 2 + j;
            unsigned int b = (i < 8) ? (mb0 >> (i * 4)) : (mb1 >> ((i - 8) * 4));
            atomicAdd(&H[key_xform(v.x) >> 19], 1u + ((b & 1u) << 16));
            atomicAdd(&H[key_xform(v.y) >> 19], 1u + ((b & 2u) << 15));
            atomicAdd(&H[key_xform(v.z) >> 19], 1u + ((b & 4u) << 14));
            atomicAdd(&H[key_xform(v.w) >> 19], 1u + ((b & 8u) << 13));
            if (b & 1u) fsum += v.x;
            if (b & 2u) fsum += v.y;
            if (b & 4u) fsum += v.z;
            if (b & 8u) fsum += v.w;
        }
        if (cch < 6) {                     // refill the buffer just consumed
#pragma unroll
            for (int j = 0; j < 2; j++) {
                unsigned int dst = (unsigned int)__cvta_generic_to_shared(
                    &dyn[kB * (1 + (cch & 1)) + (j * kT + tid) * 4]);
                CP_ASYNC16(dst, &ov[(cch + 2) * 2048 + j * kT + tid]);
            }
        }
        CP_COMMIT();                       // one group per iteration (may be empty)
    }
#pragma unroll
    for (int off = 16; off > 0; off >>= 1)
        fsum += __shfl_down_sync(0xFFFFFFFFu, fsum, off);
    if (lane == 0) swf[warp] = fsum;
    __syncthreads();                       // all atomics + buffer use complete
    if (warp == 0) {
        float f = swf[lane];
#pragma unroll
        for (int off = 16; off > 0; off >>= 1)
            f += __shfl_down_sync(0xFFFFFFFFu, f, off);
        if (lane == 0) g_pS1[bid] = (double)f;
    }
    __syncthreads();

    // ---- inclusive scans of totals / masked over kB buckets ----
    unsigned int runT = 0, runM = 0;
    int base = tid * 8;
#pragma unroll
    for (int i = 0; i < 8; i++) {
        unsigned int h = H[base + i];
        runT += h & 0xFFFFu; runM += h >> 16;
        T[base + i] = runT;  M[base + i] = runM;
    }
    unsigned int iT = runT, iM = runM;
#pragma unroll
    for (int off = 1; off < 32; off <<= 1) {
        unsigned int a = __shfl_up_sync(0xFFFFFFFFu, iT, off);
        unsigned int b = __shfl_up_sync(0xFFFFFFFFu, iM, off);
        if (lane >= off) { iT += a; iM += b; }
    }
    if (lane == 31) { swu[warp] = iT; swu2[warp] = iM; }
    __syncthreads();
    if (warp == 0) {
        unsigned int a = swu[lane], b = swu2[lane];
#pragma unroll
        for (int off = 1; off < 32; off <<= 1) {
            unsigned int x = __shfl_up_sync(0xFFFFFFFFu, a, off);
            unsigned int y = __shfl_up_sync(0xFFFFFFFFu, b, off);
            if (lane >= off) { a += x; b += y; }
        }
        swu[lane] = a; swu2[lane] = b;
        if (lane == 31) {                 // total masked count = Mc
            sMc = b;
            if (l == 0) g_Mc[c] = b;
        }
    }
    __syncthreads();
    unsigned int offT = (warp ? swu[warp - 1] : 0u) + iT - runT;
    unsigned int offM = (warp ? swu2[warp - 1] : 0u) + iM - runM;
#pragma unroll
    for (int i = 0; i < 8; i++) { T[base + i] += offT; M[base + i] += offM; }
    __syncthreads();

    // ---- 255 boundaries: precomputed rank -> masked-prefix lookup ----
    double contrib = 0.0;
    if (tid < 255) {
        unsigned int s1 = s1arr[tid];
        if (s1 != kSent) {
            double cm = 0.0;
            if (s1 > 0) {
                int blo = 0, bhi = kB - 1;           // min B with T[B] >= s1
                while (blo < bhi) { int bm = (blo + bhi) >> 1;
                                    if (T[bm] >= s1) bhi = bm; else blo = bm + 1; }
                unsigned int pT = blo ? T[blo - 1] : 0u, pM = blo ? M[blo - 1] : 0u;
                unsigned int nB = T[blo] - pT, mB = M[blo] - pM;
                unsigned int mm = s1 - pT;
                cm = (double)pM + (nB ? (double)mB * (double)mm / (double)nB : 0.0);
            }
            contrib = (double)sMc - cm;
        }
    }
#pragma unroll
    for (int off = 16; off > 0; off >>= 1)
        contrib += __shfl_down_sync(0xFFFFFFFFu, contrib, off);
    if (lane == 0) swd[warp] = contrib;
    __syncthreads();
    if (warp == 0) {
        double d = swd[lane];
#pragma unroll
        for (int off = 16; off > 0; off >>= 1)
            d += __shfl_down_sync(0xFFFFFFFFu, d, off);
        if (lane == 0) {
            float lov = ((l == 0) ? mn0 : (l == 1) ? mn1 : mn2)[c];
            float hiv = ((l == 0) ? mx0 : (l == 1) ? mx1 : mx2)[c];
            g_pS2[bid] = (double)sMc * (double)lov +
                         (double)(hiv - lov) * (1.0 / 255.0) * d;
        }
    }

    // ---- last-arriving CTA folds the 768 partials into the scalar loss ----
    __syncthreads();
    if (tid == 0) {
        __threadfence();                       // publish g_pS1/g_pS2/g_Mc
        sticket = atomicAdd(&g_done, 1u);
    }
    __syncthreads();
    if (sticket == (unsigned int)(kSegs - 1) && warp == 0) {
        __threadfence();                       // acquire all partials
        double a0 = 0, a1 = 0, a2 = 0, b0 = 0, b1 = 0, b2 = 0, cnt = 0;
        for (int s = lane; s < kSegs; s += 32) {
            int ll = s % 3;
            double v1 = g_pS1[s], v2 = g_pS2[s];
            if (ll == 0)      { a0 += v1; b0 += v2; }
            else if (ll == 1) { a1 += v1; b1 += v2; }
            else              { a2 += v1; b2 += v2; }
        }
        for (int cc = lane; cc < kC; cc += 32) cnt += (double)g_Mc[cc];
#pragma unroll
        for (int off = 16; off > 0; off >>= 1) {
            a0 += __shfl_down_sync(0xFFFFFFFFu, a0, off);
            a1 += __shfl_down_sync(0xFFFFFFFFu, a1, off);
            a2 += __shfl_down_sync(0xFFFFFFFFu, a2, off);
            b0 += __shfl_down_sync(0xFFFFFFFFu, b0, off);
            b1 += __shfl_down_sync(0xFFFFFFFFu, b1, off);
            b2 += __shfl_down_sync(0xFFFFFFFFu, b2, off);
            cnt += __shfl_down_sync(0xFFFFFFFFu, cnt, off);
        }
        if (lane == 0) {
            double loss = (double)w[0] * ((a0 - b0) / cnt) +
                          (double)w[1] * ((a1 - b1) / cnt) +
                          (double)w[2] * ((a2 - b2) / cnt);
            out[0] = (float)loss;
            g_done = 0u;                      // reset for next graph replay
        }
    }
}

extern "C" void kernel_launch(void* const* d_in, const int* in_sizes, int n_in,
                              void* d_out, int out_size) {
    (void)n_in; (void)out_size;
    int iopt[3], ihist[3], imin[3], imax[3];
    if (in_sizes[1] == kC * kBins) {       // dict (interleaved) order
        for (int l = 0; l < 3; l++) { iopt[l] = 4*l; ihist[l] = 4*l+1; imin[l] = 4*l+2; imax[l] = 4*l+3; }
    } else {                               // signature order
        for (int l = 0; l < 3; l++) { iopt[l] = l; ihist[l] = 3+l; imin[l] = 6+l; imax[l] = 9+l; }
    }
    const int iw = 12, imask = 13;

    static int smem_set = 0;
    if (!smem_set) {
        cudaFuncSetAttribute(fused_kernel, cudaFuncAttributeMaxDynamicSharedMemorySize,
                             3 * kB * sizeof(unsigned int));
        smem_set = 1;
    }

    fused_kernel<<<kSegs, kT, 3 * kB * sizeof(unsigned int)>>>(
        (const float*)d_in[iopt[0]], (const float*)d_in[iopt[1]], (const float*)d_in[iopt[2]],
        (const float*)d_in[ihist[0]], (const float*)d_in[ihist[1]], (const float*)d_in[ihist[2]],
        (const float*)d_in[imin[0]], (const float*)d_in[imin[1]], (const float*)d_in[imin[2]],
        (const float*)d_in[imax[0]], (const float*)d_in[imax[1]], (const float*)d_in[imax[2]],
        (const int*)d_in[imask], (const float*)d_in[iw], (float*)d_out);
}

// round 13
// speedup vs baseline: 1.2795x; 1.2795x over previous
#include <cuda_runtime.h>
#include <stdint.h>

static const int kC = 256, kHW = 65536, kBins = 256;
static const int kB = 4096;                // value buckets (top-12 key bits)
static const int kSegs = 768;
static const int kT = 1024;                // threads per CTA (max warps/SM)
static const unsigned int kSent = 0xFFFFFFFFu;

__device__ double       g_pS1[kSegs];
__device__ double       g_pS2[kSegs];
__device__ unsigned int g_Mc[kC];
__device__ unsigned int g_done;            // zero at load; reset by last block

// bucket = top-12 bits of the order-preserving key transform (branch-free)
__device__ __forceinline__ unsigned int bucket_of(float f) {
    unsigned int u = __float_as_uint(f);
    unsigned int s = u >> 20;
    unsigned int m = 0x800u | (((unsigned int)((int)u >> 31)) & 0x7FFu);
    return s ^ m;
}

// f32 quantile target: t_r = ((float)r * 2^-16) * total  (monotone in r)
__device__ __forceinline__ float t_of(int r, float total) {
    return ((float)r * 0x1p-16f) * total;
}

__global__ void __launch_bounds__(kT, 2) fused_kernel(
    const float* __restrict__ o0, const float* __restrict__ o1, const float* __restrict__ o2,
    const float* __restrict__ h0, const float* __restrict__ h1, const float* __restrict__ h2,
    const float* __restrict__ mn0, const float* __restrict__ mn1, const float* __restrict__ mn2,
    const float* __restrict__ mx0, const float* __restrict__ mx1, const float* __restrict__ mx2,
    const int* __restrict__ mask, const float* __restrict__ w, float* __restrict__ out) {
    extern __shared__ unsigned int dyn[];
    unsigned int* H = dyn;                 // packed: tot | masked<<16
    unsigned int* T = dyn + kB;            // inclusive scan of totals
    unsigned int* M = dyn + 2 * kB;        // inclusive scan of masked
    __shared__ float        cdf[256];
    __shared__ unsigned int s1arr[256];    // boundary ranks (kSent = no contribution)
    __shared__ float        swf[32];
    __shared__ unsigned int swu[32], swu2[32];
    __shared__ double       swd[32];
    __shared__ unsigned int sMc, sticket;
    __shared__ float        sTotal;

    int bid = blockIdx.x;
    int c = bid / 3, l = bid % 3;          // 3 levels of a channel adjacent -> mask L2 reuse
    const float* opt = (l == 0) ? o0 : (l == 1) ? o1 : o2;
    int tid = threadIdx.x, lane = tid & 31, warp = tid >> 5;

    for (int i = tid; i < kB; i += kT) H[i] = 0u;

    // ---- parallel target-CDF build (warp 0): 8 bins/lane + shuffle scan ----
    const float* hist = ((l == 0) ? h0 : (l == 1) ? h1 : h2) + (size_t)c * kBins;
    if (warp == 0) {
        const float4* hv = reinterpret_cast<const float4*>(hist);
        float4 a = hv[lane * 2], b = hv[lane * 2 + 1];
        float v[8] = {a.x, a.y, a.z, a.w, b.x, b.y, b.z, b.w};
        float run = 0.f, pref[8];
#pragma unroll
        for (int i = 0; i < 8; i++) { run += v[i]; pref[i] = run; }
        float incl = run;
#pragma unroll
        for (int off = 1; off < 32; off <<= 1) {
            float o = __shfl_up_sync(0xFFFFFFFFu, incl, off);
            if (lane >= off) incl += o;
        }
        float excl = incl - run;
#pragma unroll
        for (int i = 0; i < 8; i++) cdf[lane * 8 + i] = excl + pref[i];
        if (lane == 31) sTotal = incl;
    }
    __syncthreads();   // H zeroed, cdf + sTotal ready

    // ---- boundary ranks (overlaps with histogram start on other warps) ----
    if (tid < 255) {
        float cj = cdf[tid], total = sTotal;
        unsigned int s1 = kSent;
        if (t_of(65536, total) > cj) {
            int lo = 1, hi = 65536;                  // min r with t_r > cj
            while (lo < hi) { int mid = (lo + hi) >> 1;
                              if (t_of(mid, total) > cj) hi = mid; else lo = mid + 1; }
            s1 = (unsigned int)(lo - 1);
        }
        s1arr[tid] = s1;
    }

    // ---- Phase A: compress 64 mask bits/thread into 2 regs (deep LDG batch) ----
    const float4* ov = reinterpret_cast<const float4*>(opt) + (size_t)c * (kHW / 4);
    const int4*   mv = reinterpret_cast<const int4*>(mask)  + (size_t)c * (kHW / 4);
    unsigned int mb0 = 0u, mb1 = 0u;
#pragma unroll
    for (int i = 0; i < 8; i++) {
        int4 m = mv[tid + kT * i];
        unsigned int b = (m.x ? 1u : 0u) | (m.y ? 2u : 0u) | (m.z ? 4u : 0u) | (m.w ? 8u : 0u);
        mb0 |= b << (i * 4);
    }
#pragma unroll
    for (int i = 0; i < 8; i++) {
        int4 m = mv[tid + kT * (8 + i)];
        unsigned int b = (m.x ? 1u : 0u) | (m.y ? 2u : 0u) | (m.z ? 4u : 0u) | (m.w ? 8u : 0u);
        mb1 |= b << (i * 4);
    }

    // ---- Phase B: streaming opt loads + smem atomics, mask from registers ----
    float fsum = 0.f;
#pragma unroll 4
    for (int i = 0; i < 16; i++) {
        float4 v = __ldcs(&ov[tid + kT * i]);     // streaming: no L2 pollution
        unsigned int b = (i < 8) ? (mb0 >> (i * 4)) : (mb1 >> ((i - 8) * 4));
        atomicAdd(&H[bucket_of(v.x)], 1u + ((b & 1u) << 16));
        atomicAdd(&H[bucket_of(v.y)], 1u + ((b & 2u) << 15));
        atomicAdd(&H[bucket_of(v.z)], 1u + ((b & 4u) << 14));
        atomicAdd(&H[bucket_of(v.w)], 1u + ((b & 8u) << 13));
        if (b & 1u) fsum += v.x;
        if (b & 2u) fsum += v.y;
        if (b & 4u) fsum += v.z;
        if (b & 8u) fsum += v.w;
    }
#pragma unroll
    for (int off = 16; off > 0; off >>= 1)
        fsum += __shfl_down_sync(0xFFFFFFFFu, fsum, off);
    if (lane == 0) swf[warp] = fsum;
    __syncthreads();
    if (warp == 0) {
        float f = swf[lane];
#pragma unroll
        for (int off = 16; off > 0; off >>= 1)
            f += __shfl_down_sync(0xFFFFFFFFu, f, off);
        if (lane == 0) g_pS1[bid] = (double)f;
    }
    __syncthreads();

    // ---- inclusive scans of totals / masked over kB buckets ----
    unsigned int runT = 0, runM = 0;
    int base = tid * 4;
#pragma unroll
    for (int i = 0; i < 4; i++) {
        unsigned int h = H[base + i];
        runT += h & 0xFFFFu; runM += h >> 16;
        T[base + i] = runT;  M[base + i] = runM;
    }
    unsigned int iT = runT, iM = runM;
#pragma unroll
    for (int off = 1; off < 32; off <<= 1) {
        unsigned int a = __shfl_up_sync(0xFFFFFFFFu, iT, off);
        unsigned int b = __shfl_up_sync(0xFFFFFFFFu, iM, off);
        if (lane >= off) { iT += a; iM += b; }
    }
    if (lane == 31) { swu[warp] = iT; swu2[warp] = iM; }
    __syncthreads();
    if (warp == 0) {
        unsigned int a = swu[lane], b = swu2[lane];
#pragma unroll
        for (int off = 1; off < 32; off <<= 1) {
            unsigned int x = __shfl_up_sync(0xFFFFFFFFu, a, off);
            unsigned int y = __shfl_up_sync(0xFFFFFFFFu, b, off);
            if (lane >= off) { a += x; b += y; }
        }
        swu[lane] = a; swu2[lane] = b;
        if (lane == 31) {                 // total masked count = Mc
            sMc = b;
            if (l == 0) g_Mc[c] = b;
        }
    }
    __syncthreads();
    unsigned int offT = (warp ? swu[warp - 1] : 0u) + iT - runT;
    unsigned int offM = (warp ? swu2[warp - 1] : 0u) + iM - runM;
#pragma unroll
    for (int i = 0; i < 4; i++) { T[base + i] += offT; M[base + i] += offM; }
    __syncthreads();

    // ---- 255 boundaries: precomputed rank -> masked-prefix lookup ----
    double contrib = 0.0;
    if (tid < 255) {
        unsigned int s1 = s1arr[tid];
        if (s1 != kSent) {
            double cm = 0.0;
            if (s1 > 0) {
                int blo = 0, bhi = kB - 1;           // min B with T[B] >= s1
                while (blo < bhi) { int bm = (blo + bhi) >> 1;
                                    if (T[bm] >= s1) bhi = bm; else blo = bm + 1; }
                unsigned int pT = blo ? T[blo - 1] : 0u, pM = blo ? M[blo - 1] : 0u;
                unsigned int nB = T[blo] - pT, mB = M[blo] - pM;
                unsigned int mm = s1 - pT;
                cm = (double)pM + (nB ? (double)mB * (double)mm / (double)nB : 0.0);
            }
            contrib = (double)sMc - cm;
        }
    }
#pragma unroll
    for (int off = 16; off > 0; off >>= 1)
        contrib += __shfl_down_sync(0xFFFFFFFFu, contrib, off);
    if (lane == 0) swd[warp] = contrib;
    __syncthreads();
    if (warp == 0) {
        double d = swd[lane];
#pragma unroll
        for (int off = 16; off > 0; off >>= 1)
            d += __shfl_down_sync(0xFFFFFFFFu, d, off);
        if (lane == 0) {
            float lov = ((l == 0) ? mn0 : (l == 1) ? mn1 : mn2)[c];
            float hiv = ((l == 0) ? mx0 : (l == 1) ? mx1 : mx2)[c];
            g_pS2[bid] = (double)sMc * (double)lov +
                         (double)(hiv - lov) * (1.0 / 255.0) * d;
        }
    }

    // ---- last-arriving CTA folds the 768 partials into the scalar loss ----
    __syncthreads();
    if (tid == 0) {
        __threadfence();                       // publish g_pS1/g_pS2/g_Mc
        sticket = atomicAdd(&g_done, 1u);
    }
    __syncthreads();
    if (sticket == (unsigned int)(kSegs - 1) && warp == 0) {
        __threadfence();                       // acquire all partials
        double a0 = 0, a1 = 0, a2 = 0, b0 = 0, b1 = 0, b2 = 0, cnt = 0;
        for (int s = lane; s < kSegs; s += 32) {
            int ll = s % 3;
            double v1 = g_pS1[s], v2 = g_pS2[s];
            if (ll == 0)      { a0 += v1; b0 += v2; }
            else if (ll == 1) { a1 += v1; b1 += v2; }
            else              { a2 += v1; b2 += v2; }
        }
        for (int cc = lane; cc < kC; cc += 32) cnt += (double)g_Mc[cc];
#pragma unroll
        for (int off = 16; off > 0; off >>= 1) {
            a0 += __shfl_down_sync(0xFFFFFFFFu, a0, off);
            a1 += __shfl_down_sync(0xFFFFFFFFu, a1, off);
            a2 += __shfl_down_sync(0xFFFFFFFFu, a2, off);
            b0 += __shfl_down_sync(0xFFFFFFFFu, b0, off);
            b1 += __shfl_down_sync(0xFFFFFFFFu, b1, off);
            b2 += __shfl_down_sync(0xFFFFFFFFu, b2, off);
            cnt += __shfl_down_sync(0xFFFFFFFFu, cnt, off);
        }
        if (lane == 0) {
            double loss = (double)w[0] * ((a0 - b0) / cnt) +
                          (double)w[1] * ((a1 - b1) / cnt) +
                          (double)w[2] * ((a2 - b2) / cnt);
            out[0] = (float)loss;
            g_done = 0u;                      // reset for next graph replay
        }
    }
}

extern "C" void kernel_launch(void* const* d_in, const int* in_sizes, int n_in,
                              void* d_out, int out_size) {
    (void)n_in; (void)out_size;
    int iopt[3], ihist[3], imin[3], imax[3];
    if (in_sizes[1] == kC * kBins) {       // dict (interleaved) order
        for (int l = 0; l < 3; l++) { iopt[l] = 4*l; ihist[l] = 4*l+1; imin[l] = 4*l+2; imax[l] = 4*l+3; }
    } else {                               // signature order
        for (int l = 0; l < 3; l++) { iopt[l] = l; ihist[l] = 3+l; imin[l] = 6+l; imax[l] = 9+l; }
    }
    const int iw = 12, imask = 13;

    static int smem_set = 0;
    if (!smem_set) {
        cudaFuncSetAttribute(fused_kernel, cudaFuncAttributeMaxDynamicSharedMemorySize,
                             3 * kB * sizeof(unsigned int));
        smem_set = 1;
    }

    fused_kernel<<<kSegs, kT, 3 * kB * sizeof(unsigned int)>>>(
        (const float*)d_in[iopt[0]], (const float*)d_in[iopt[1]], (const float*)d_in[iopt[2]],
        (const float*)d_in[ihist[0]], (const float*)d_in[ihist[1]], (const float*)d_in[ihist[2]],
        (const float*)d_in[imin[0]], (const float*)d_in[imin[1]], (const float*)d_in[imin[2]],
        (const float*)d_in[imax[0]], (const float*)d_in[imax[1]], (const float*)d_in[imax[2]],
        (const int*)d_in[imask], (const float*)d_in[iw], (float*)d_out);
}

// round 14
// speedup vs baseline: 1.2955x; 1.0125x over previous
#include <cuda_runtime.h>
#include <stdint.h>

static const int kC = 256, kHW = 65536, kBins = 256;
static const int kB = 2048;                // value buckets (top-11 key bits)
static const int kSegs = 768;
static const int kT = 1024;                // threads per CTA (max warps/SM)
static const unsigned int kSent = 0xFFFFFFFFu;

__device__ double       g_pS1[kSegs];
__device__ double       g_pS2[kSegs];
__device__ unsigned int g_Mc[kC];
__device__ unsigned int g_done;            // zero at load; reset by last block

// bucket = top-11 bits of the order-preserving key transform (branch-free)
__device__ __forceinline__ unsigned int bucket_of(float f) {
    unsigned int u = __float_as_uint(f);
    unsigned int s = u >> 21;
    unsigned int m = 0x400u | (((unsigned int)((int)u >> 31)) & 0x3FFu);
    return s ^ m;
}

// f32 quantile target: t_r = ((float)r * 2^-16) * total  (monotone in r)
__device__ __forceinline__ float t_of(int r, float total) {
    return ((float)r * 0x1p-16f) * total;
}

__global__ void __launch_bounds__(kT, 2) fused_kernel(
    const float* __restrict__ o0, const float* __restrict__ o1, const float* __restrict__ o2,
    const float* __restrict__ h0, const float* __restrict__ h1, const float* __restrict__ h2,
    const float* __restrict__ mn0, const float* __restrict__ mn1, const float* __restrict__ mn2,
    const float* __restrict__ mx0, const float* __restrict__ mx1, const float* __restrict__ mx2,
    const int* __restrict__ mask, const float* __restrict__ w, float* __restrict__ out) {
    extern __shared__ unsigned int dyn[];
    unsigned int* H = dyn;                 // packed: tot | masked<<16
    unsigned int* T = dyn + kB;            // inclusive scan of totals
    unsigned int* M = dyn + 2 * kB;        // inclusive scan of masked
    __shared__ float        cdf[256];
    __shared__ unsigned int s1arr[256];    // boundary ranks (kSent = no contribution)
    __shared__ float        swf[32];
    __shared__ unsigned int swu[32], swu2[32];
    __shared__ double       swd[32];
    __shared__ unsigned int sMc, sticket;
    __shared__ float        sTotal;

    int bid = blockIdx.x;
    int c = bid / 3, l = bid % 3;          // 3 levels of a channel adjacent -> mask L2 reuse
    const float* opt = (l == 0) ? o0 : (l == 1) ? o1 : o2;
    int tid = threadIdx.x, lane = tid & 31, warp = tid >> 5;

    for (int i = tid; i < kB; i += kT) H[i] = 0u;

    // ---- parallel target-CDF build (warp 0): 8 bins/lane + shuffle scan ----
    const float* hist = ((l == 0) ? h0 : (l == 1) ? h1 : h2) + (size_t)c * kBins;
    if (warp == 0) {
        const float4* hv = reinterpret_cast<const float4*>(hist);
        float4 a = hv[lane * 2], b = hv[lane * 2 + 1];
        float v[8] = {a.x, a.y, a.z, a.w, b.x, b.y, b.z, b.w};
        float run = 0.f, pref[8];
#pragma unroll
        for (int i = 0; i < 8; i++) { run += v[i]; pref[i] = run; }
        float incl = run;
#pragma unroll
        for (int off = 1; off < 32; off <<= 1) {
            float o = __shfl_up_sync(0xFFFFFFFFu, incl, off);
            if (lane >= off) incl += o;
        }
        float excl = incl - run;
#pragma unroll
        for (int i = 0; i < 8; i++) cdf[lane * 8 + i] = excl + pref[i];
        if (lane == 31) sTotal = incl;
    }
    __syncthreads();   // H zeroed, cdf + sTotal ready

    // ---- boundary ranks (overlaps with histogram start on other warps) ----
    if (tid < 255) {
        float cj = cdf[tid], total = sTotal;
        unsigned int s1 = kSent;
        if (t_of(65536, total) > cj) {
            int lo = 1, hi = 65536;                  // min r with t_r > cj
            while (lo < hi) { int mid = (lo + hi) >> 1;
                              if (t_of(mid, total) > cj) hi = mid; else lo = mid + 1; }
            s1 = (unsigned int)(lo - 1);
        }
        s1arr[tid] = s1;
    }

    // ---- Phase A: compress 64 mask bits/thread into 2 regs (deep LDG batch) ----
    const float4* ov = reinterpret_cast<const float4*>(opt) + (size_t)c * (kHW / 4);
    const int4*   mv = reinterpret_cast<const int4*>(mask)  + (size_t)c * (kHW / 4);
    unsigned int mb0 = 0u, mb1 = 0u;
#pragma unroll
    for (int i = 0; i < 8; i++) {
        int4 m = mv[tid + kT * i];
        unsigned int b = (m.x ? 1u : 0u) | (m.y ? 2u : 0u) | (m.z ? 4u : 0u) | (m.w ? 8u : 0u);
        mb0 |= b << (i * 4);
    }
#pragma unroll
    for (int i = 0; i < 8; i++) {
        int4 m = mv[tid + kT * (8 + i)];
        unsigned int b = (m.x ? 1u : 0u) | (m.y ? 2u : 0u) | (m.z ? 4u : 0u) | (m.w ? 8u : 0u);
        mb1 |= b << (i * 4);
    }

    // ---- Phase B: streaming opt loads + smem atomics, mask from registers ----
    float fsum = 0.f;
#pragma unroll 4
    for (int i = 0; i < 16; i++) {
        float4 v = __ldcs(&ov[tid + kT * i]);     // streaming: no L2 pollution
        unsigned int b = (i < 8) ? (mb0 >> (i * 4)) : (mb1 >> ((i - 8) * 4));
        atomicAdd(&H[bucket_of(v.x)], 1u + ((b & 1u) << 16));
        atomicAdd(&H[bucket_of(v.y)], 1u + ((b & 2u) << 15));
        atomicAdd(&H[bucket_of(v.z)], 1u + ((b & 4u) << 14));
        atomicAdd(&H[bucket_of(v.w)], 1u + ((b & 8u) << 13));
        if (b & 1u) fsum += v.x;
        if (b & 2u) fsum += v.y;
        if (b & 4u) fsum += v.z;
        if (b & 8u) fsum += v.w;
    }
#pragma unroll
    for (int off = 16; off > 0; off >>= 1)
        fsum += __shfl_down_sync(0xFFFFFFFFu, fsum, off);
    if (lane == 0) swf[warp] = fsum;
    __syncthreads();
    if (warp == 0) {
        float f = swf[lane];
#pragma unroll
        for (int off = 16; off > 0; off >>= 1)
            f += __shfl_down_sync(0xFFFFFFFFu, f, off);
        if (lane == 0) g_pS1[bid] = (double)f;
    }
    __syncthreads();

    // ---- inclusive scans of totals / masked over kB buckets ----
    unsigned int runT = 0, runM = 0;
    int base = tid * 2;
    {
        unsigned int h0v = H[base], h1v = H[base + 1];
        runT = (h0v & 0xFFFFu); runM = (h0v >> 16);
        T[base] = runT; M[base] = runM;
        runT += (h1v & 0xFFFFu); runM += (h1v >> 16);
        T[base + 1] = runT; M[base + 1] = runM;
    }
    unsigned int iT = runT, iM = runM;
#pragma unroll
    for (int off = 1; off < 32; off <<= 1) {
        unsigned int a = __shfl_up_sync(0xFFFFFFFFu, iT, off);
        unsigned int b = __shfl_up_sync(0xFFFFFFFFu, iM, off);
        if (lane >= off) { iT += a; iM += b; }
    }
    if (lane == 31) { swu[warp] = iT; swu2[warp] = iM; }
    __syncthreads();
    if (warp == 0) {
        unsigned int a = swu[lane], b = swu2[lane];
#pragma unroll
        for (int off = 1; off < 32; off <<= 1) {
            unsigned int x = __shfl_up_sync(0xFFFFFFFFu, a, off);
            unsigned int y = __shfl_up_sync(0xFFFFFFFFu, b, off);
            if (lane >= off) { a += x; b += y; }
        }
        swu[lane] = a; swu2[lane] = b;
        if (lane == 31) {                 // total masked count = Mc
            sMc = b;
            if (l == 0) g_Mc[c] = b;
        }
    }
    __syncthreads();
    unsigned int offT = (warp ? swu[warp - 1] : 0u) + iT - runT;
    unsigned int offM = (warp ? swu2[warp - 1] : 0u) + iM - runM;
    T[base] += offT; T[base + 1] += offT;
    M[base] += offM; M[base + 1] += offM;
    __syncthreads();

    // ---- 255 boundaries: precomputed rank -> masked-prefix lookup ----
    double contrib = 0.0;
    if (tid < 255) {
        unsigned int s1 = s1arr[tid];
        if (s1 != kSent) {
            double cm = 0.0;
            if (s1 > 0) {
                int blo = 0, bhi = kB - 1;           // min B with T[B] >= s1
                while (blo < bhi) { int bm = (blo + bhi) >> 1;
                                    if (T[bm] >= s1) bhi = bm; else blo = bm + 1; }
                unsigned int pT = blo ? T[blo - 1] : 0u, pM = blo ? M[blo - 1] : 0u;
                unsigned int nB = T[blo] - pT, mB = M[blo] - pM;
                unsigned int mm = s1 - pT;
                cm = (double)pM + (nB ? (double)mB * (double)mm / (double)nB : 0.0);
            }
            contrib = (double)sMc - cm;
        }
    }
#pragma unroll
    for (int off = 16; off > 0; off >>= 1)
        contrib += __shfl_down_sync(0xFFFFFFFFu, contrib, off);
    if (lane == 0) swd[warp] = contrib;
    __syncthreads();
    if (warp == 0) {
        double d = swd[lane];
#pragma unroll
        for (int off = 16; off > 0; off >>= 1)
            d += __shfl_down_sync(0xFFFFFFFFu, d, off);
        if (lane == 0) {
            float lov = ((l == 0) ? mn0 : (l == 1) ? mn1 : mn2)[c];
            float hiv = ((l == 0) ? mx0 : (l == 1) ? mx1 : mx2)[c];
            g_pS2[bid] = (double)sMc * (double)lov +
                         (double)(hiv - lov) * (1.0 / 255.0) * d;
        }
    }

    // ---- last-arriving CTA folds the 768 partials into the scalar loss ----
    __syncthreads();
    if (tid == 0) {
        __threadfence();                       // publish g_pS1/g_pS2/g_Mc
        sticket = atomicAdd(&g_done, 1u);
    }
    __syncthreads();
    if (sticket == (unsigned int)(kSegs - 1) && warp == 0) {
        __threadfence();                       // acquire all partials
        double a0 = 0, a1 = 0, a2 = 0, b0 = 0, b1 = 0, b2 = 0, cnt = 0;
        for (int s = lane; s < kSegs; s += 32) {
            int ll = s % 3;
            double v1 = g_pS1[s], v2 = g_pS2[s];
            if (ll == 0)      { a0 += v1; b0 += v2; }
            else if (ll == 1) { a1 += v1; b1 += v2; }
            else              { a2 += v1; b2 += v2; }
        }
        for (int cc = lane; cc < kC; cc += 32) cnt += (double)g_Mc[cc];
#pragma unroll
        for (int off = 16; off > 0; off >>= 1) {
            a0 += __shfl_down_sync(0xFFFFFFFFu, a0, off);
            a1 += __shfl_down_sync(0xFFFFFFFFu, a1, off);
            a2 += __shfl_down_sync(0xFFFFFFFFu, a2, off);
            b0 += __shfl_down_sync(0xFFFFFFFFu, b0, off);
            b1 += __shfl_down_sync(0xFFFFFFFFu, b1, off);
            b2 += __shfl_down_sync(0xFFFFFFFFu, b2, off);
            cnt += __shfl_down_sync(0xFFFFFFFFu, cnt, off);
        }
        if (lane == 0) {
            double loss = (double)w[0] * ((a0 - b0) / cnt) +
                          (double)w[1] * ((a1 - b1) / cnt) +
                          (double)w[2] * ((a2 - b2) / cnt);
            out[0] = (float)loss;
            g_done = 0u;                      // reset for next graph replay
        }
    }
}

extern "C" void kernel_launch(void* const* d_in, const int* in_sizes, int n_in,
                              void* d_out, int out_size) {
    (void)n_in; (void)out_size;
    int iopt[3], ihist[3], imin[3], imax[3];
    if (in_sizes[1] == kC * kBins) {       // dict (interleaved) order
        for (int l = 0; l < 3; l++) { iopt[l] = 4*l; ihist[l] = 4*l+1; imin[l] = 4*l+2; imax[l] = 4*l+3; }
    } else {                               // signature order
        for (int l = 0; l < 3; l++) { iopt[l] = l; ihist[l] = 3+l; imin[l] = 6+l; imax[l] = 9+l; }
    }
    const int iw = 12, imask = 13;

    static int smem_set = 0;
    if (!smem_set) {
        cudaFuncSetAttribute(fused_kernel, cudaFuncAttributeMaxDynamicSharedMemorySize,
                             3 * kB * sizeof(unsigned int));
        smem_set = 1;
    }

    fused_kernel<<<kSegs, kT, 3 * kB * sizeof(unsigned int)>>>(
        (const float*)d_in[iopt[0]], (const float*)d_in[iopt[1]], (const float*)d_in[iopt[2]],
        (const float*)d_in[ihist[0]], (const float*)d_in[ihist[1]], (const float*)d_in[ihist[2]],
        (const float*)d_in[imin[0]], (const float*)d_in[imin[1]], (const float*)d_in[imin[2]],
        (const float*)d_in[imax[0]], (const float*)d_in[imax[1]], (const float*)d_in[imax[2]],
        (const int*)d_in[imask], (const float*)d_in[iw], (float*)d_out);
}

// round 16
// speedup vs baseline: 1.3696x; 1.0572x over previous
#include <cuda_runtime.h>
#include <stdint.h>

static const int kC = 256, kHW = 65536, kBins = 256;
static const int kB = 2048;                // value buckets (top-11 key bits)
static const int kSegs = 768;
static const int kT = 1024;                // threads per CTA (max warps/SM)
static const unsigned int kSent = 0xFFFFFFFFu;

__device__ double       g_pS1[kSegs];
__device__ double       g_pS2[kSegs];
__device__ unsigned int g_Mc[kC];
__device__ unsigned int g_done;            // zero at load; reset by last block

// bucket = top-11 bits of the order-preserving key transform (branch-free)
__device__ __forceinline__ unsigned int bucket_of(float f) {
    unsigned int u = __float_as_uint(f);
    unsigned int s = u >> 21;
    unsigned int m = 0x400u | (((unsigned int)((int)u >> 31)) & 0x3FFu);
    return s ^ m;
}

// f32 quantile target: t_r = ((float)r * 2^-16) * total  (monotone in r)
__device__ __forceinline__ float t_of(int r, float total) {
    return ((float)r * 0x1p-16f) * total;
}

__global__ void __launch_bounds__(kT, 2) fused_kernel(
    const float* __restrict__ o0, const float* __restrict__ o1, const float* __restrict__ o2,
    const float* __restrict__ h0, const float* __restrict__ h1, const float* __restrict__ h2,
    const float* __restrict__ mn0, const float* __restrict__ mn1, const float* __restrict__ mn2,
    const float* __restrict__ mx0, const float* __restrict__ mx1, const float* __restrict__ mx2,
    const int* __restrict__ mask, const float* __restrict__ w, float* __restrict__ out) {
    extern __shared__ unsigned int dyn[];
    unsigned int* H = dyn;                 // packed: tot | masked<<16
    unsigned int* T = dyn + kB;            // inclusive scan of totals
    unsigned int* M = dyn + 2 * kB;        // inclusive scan of masked
    __shared__ float        cdf[256];
    __shared__ unsigned int s1arr[256];    // boundary ranks (kSent = no contribution)
    __shared__ float        swf[32];
    __shared__ unsigned int swu[32], swu2[32];
    __shared__ double       swd[32];
    __shared__ unsigned int sMc, sticket;
    __shared__ float        sTotal;

    int bid = blockIdx.x;
    int c = bid / 3, l = bid % 3;          // 3 levels of a channel adjacent -> mask L2 reuse
    const float* opt = (l == 0) ? o0 : (l == 1) ? o1 : o2;
    int tid = threadIdx.x, lane = tid & 31, warp = tid >> 5;

    for (int i = tid; i < kB; i += kT) H[i] = 0u;

    // ---- parallel target-CDF build (warp 0): 8 bins/lane + shuffle scan ----
    const float* hist = ((l == 0) ? h0 : (l == 1) ? h1 : h2) + (size_t)c * kBins;
    if (warp == 0) {
        const float4* hv = reinterpret_cast<const float4*>(hist);
        float4 a = hv[lane * 2], b = hv[lane * 2 + 1];
        float v[8] = {a.x, a.y, a.z, a.w, b.x, b.y, b.z, b.w};
        float run = 0.f, pref[8];
#pragma unroll
        for (int i = 0; i < 8; i++) { run += v[i]; pref[i] = run; }
        float incl = run;
#pragma unroll
        for (int off = 1; off < 32; off <<= 1) {
            float o = __shfl_up_sync(0xFFFFFFFFu, incl, off);
            if (lane >= off) incl += o;
        }
        float excl = incl - run;
#pragma unroll
        for (int i = 0; i < 8; i++) cdf[lane * 8 + i] = excl + pref[i];
        if (lane == 31) sTotal = incl;
    }
    __syncthreads();   // H zeroed, cdf + sTotal ready

    // ---- boundary ranks (overlaps with histogram start on other warps) ----
    if (tid < 255) {
        float cj = cdf[tid], total = sTotal;
        unsigned int s1 = kSent;
        if (t_of(65536, total) > cj) {
            int lo = 1, hi = 65536;                  // min r with t_r > cj
            while (lo < hi) { int mid = (lo + hi) >> 1;
                              if (t_of(mid, total) > cj) hi = mid; else lo = mid + 1; }
            s1 = (unsigned int)(lo - 1);
        }
        s1arr[tid] = s1;
    }

    // ---- Phase A: compress 64 mask bits/thread into 2 regs (deep LDG batch) ----
    const float4* ov = reinterpret_cast<const float4*>(opt) + (size_t)c * (kHW / 4);
    const int4*   mv = reinterpret_cast<const int4*>(mask)  + (size_t)c * (kHW / 4);
    unsigned int mb0 = 0u, mb1 = 0u;
#pragma unroll
    for (int i = 0; i < 8; i++) {
        int4 m = mv[tid + kT * i];
        unsigned int b = (m.x ? 1u : 0u) | (m.y ? 2u : 0u) | (m.z ? 4u : 0u) | (m.w ? 8u : 0u);
        mb0 |= b << (i * 4);
    }
#pragma unroll
    for (int i = 0; i < 8; i++) {
        int4 m = mv[tid + kT * (8 + i)];
        unsigned int b = (m.x ? 1u : 0u) | (m.y ? 2u : 0u) | (m.z ? 4u : 0u) | (m.w ? 8u : 0u);
        mb1 |= b << (i * 4);
    }

    // ---- Phase B: streaming opt loads + smem atomics, mask from registers ----
    float fsum = 0.f;
#pragma unroll
    for (int i = 0; i < 16; i++) {
        float4 v = __ldcs(&ov[tid + kT * i]);     // streaming: no L2 pollution
        unsigned int b = (i < 8) ? (mb0 >> (i * 4)) : (mb1 >> ((i - 8) * 4));
        atomicAdd(&H[bucket_of(v.x)], 1u + ((b & 1u) << 16));
        atomicAdd(&H[bucket_of(v.y)], 1u + ((b & 2u) << 15));
        atomicAdd(&H[bucket_of(v.z)], 1u + ((b & 4u) << 14));
        atomicAdd(&H[bucket_of(v.w)], 1u + ((b & 8u) << 13));
        if (b & 1u) fsum += v.x;
        if (b & 2u) fsum += v.y;
        if (b & 4u) fsum += v.z;
        if (b & 8u) fsum += v.w;
    }
#pragma unroll
    for (int off = 16; off > 0; off >>= 1)
        fsum += __shfl_down_sync(0xFFFFFFFFu, fsum, off);
    if (lane == 0) swf[warp] = fsum;
    __syncthreads();
    if (warp == 0) {
        float f = swf[lane];
#pragma unroll
        for (int off = 16; off > 0; off >>= 1)
            f += __shfl_down_sync(0xFFFFFFFFu, f, off);
        if (lane == 0) g_pS1[bid] = (double)f;
    }
    __syncthreads();

    // ---- inclusive scans of totals / masked over kB buckets ----
    unsigned int runT = 0, runM = 0;
    int base = tid * 2;
    {
        unsigned int h0v = H[base], h1v = H[base + 1];
        runT = (h0v & 0xFFFFu); runM = (h0v >> 16);
        T[base] = runT; M[base] = runM;
        runT += (h1v & 0xFFFFu); runM += (h1v >> 16);
        T[base + 1] = runT; M[base + 1] = runM;
    }
    unsigned int iT = runT, iM = runM;
#pragma unroll
    for (int off = 1; off < 32; off <<= 1) {
        unsigned int a = __shfl_up_sync(0xFFFFFFFFu, iT, off);
        unsigned int b = __shfl_up_sync(0xFFFFFFFFu, iM, off);
        if (lane >= off) { iT += a; iM += b; }
    }
    if (lane == 31) { swu[warp] = iT; swu2[warp] = iM; }
    __syncthreads();
    if (warp == 0) {
        unsigned int a = swu[lane], b = swu2[lane];
#pragma unroll
        for (int off = 1; off < 32; off <<= 1) {
            unsigned int x = __shfl_up_sync(0xFFFFFFFFu, a, off);
            unsigned int y = __shfl_up_sync(0xFFFFFFFFu, b, off);
            if (lane >= off) { a += x; b += y; }
        }
        swu[lane] = a; swu2[lane] = b;
        if (lane == 31) {                 // total masked count = Mc (exact)
            sMc = b;
            if (l == 0) g_Mc[c] = b;
        }
    }
    __syncthreads();
    unsigned int offT = (warp ? swu[warp - 1] : 0u) + iT - runT;
    unsigned int offM = (warp ? swu2[warp - 1] : 0u) + iM - runM;
    T[base] += offT; T[base + 1] += offT;
    M[base] += offM; M[base + 1] += offM;
    __syncthreads();

    // ---- 255 boundaries: precomputed rank -> masked-prefix lookup ----
    double contrib = 0.0;
    if (tid < 255) {
        unsigned int s1 = s1arr[tid];
        if (s1 != kSent) {
            double cm = 0.0;
            if (s1 > 0) {
                int blo = 0, bhi = kB - 1;           // min B with T[B] >= s1
                while (blo < bhi) { int bm = (blo + bhi) >> 1;
                                    if (T[bm] >= s1) bhi = bm; else blo = bm + 1; }
                unsigned int pT = blo ? T[blo - 1] : 0u, pM = blo ? M[blo - 1] : 0u;
                unsigned int nB = T[blo] - pT, mB = M[blo] - pM;
                unsigned int mm = s1 - pT;
                cm = (double)pM + (nB ? (double)mB * (double)mm / (double)nB : 0.0);
            }
            contrib = (double)sMc - cm;
        }
    }
#pragma unroll
    for (int off = 16; off > 0; off >>= 1)
        contrib += __shfl_down_sync(0xFFFFFFFFu, contrib, off);
    if (lane == 0) swd[warp] = contrib;
    __syncthreads();
    if (warp == 0) {
        double d = swd[lane];
#pragma unroll
        for (int off = 16; off > 0; off >>= 1)
            d += __shfl_down_sync(0xFFFFFFFFu, d, off);
        if (lane == 0) {
            float lov = ((l == 0) ? mn0 : (l == 1) ? mn1 : mn2)[c];
            float hiv = ((l == 0) ? mx0 : (l == 1) ? mx1 : mx2)[c];
            g_pS2[bid] = (double)sMc * (double)lov +
                         (double)(hiv - lov) * (1.0 / 255.0) * d;
        }
    }

    // ---- last-arriving CTA folds the 768 partials into the scalar loss ----
    __syncthreads();
    if (tid == 0) {
        __threadfence();                       // publish g_pS1/g_pS2/g_Mc
        sticket = atomicAdd(&g_done, 1u);
    }
    __syncthreads();
    if (sticket == (unsigned int)(kSegs - 1) && warp == 0) {
        __threadfence();                       // acquire all partials
        double a0 = 0, a1 = 0, a2 = 0, b0 = 0, b1 = 0, b2 = 0, cnt = 0;
        for (int s = lane; s < kSegs; s += 32) {
            int ll = s % 3;
            double v1 = g_pS1[s], v2 = g_pS2[s];
            if (ll == 0)      { a0 += v1; b0 += v2; }
            else if (ll == 1) { a1 += v1; b1 += v2; }
            else              { a2 += v1; b2 += v2; }
        }
        for (int cc = lane; cc < kC; cc += 32) cnt += (double)g_Mc[cc];
#pragma unroll
        for (int off = 16; off > 0; off >>= 1) {
            a0 += __shfl_down_sync(0xFFFFFFFFu, a0, off);
            a1 += __shfl_down_sync(0xFFFFFFFFu, a1, off);
            a2 += __shfl_down_sync(0xFFFFFFFFu, a2, off);
            b0 += __shfl_down_sync(0xFFFFFFFFu, b0, off);
            b1 += __shfl_down_sync(0xFFFFFFFFu, b1, off);
            b2 += __shfl_down_sync(0xFFFFFFFFu, b2, off);
            cnt += __shfl_down_sync(0xFFFFFFFFu, cnt, off);
        }
        if (lane == 0) {
            double loss = (double)w[0] * ((a0 - b0) / cnt) +
                          (double)w[1] * ((a1 - b1) / cnt) +
                          (double)w[2] * ((a2 - b2) / cnt);
            out[0] = (float)loss;
            g_done = 0u;                      // reset for next graph replay
        }
    }
}

extern "C" void kernel_launch(void* const* d_in, const int* in_sizes, int n_in,
                              void* d_out, int out_size) {
    (void)n_in; (void)out_size;
    int iopt[3], ihist[3], imin[3], imax[3];
    if (in_sizes[1] == kC * kBins) {       // dict (interleaved) order
        for (int l = 0; l < 3; l++) { iopt[l] = 4*l; ihist[l] = 4*l+1; imin[l] = 4*l+2; imax[l] = 4*l+3; }
    } else {                               // signature order
        for (int l = 0; l < 3; l++) { iopt[l] = l; ihist[l] = 3+l; imin[l] = 6+l; imax[l] = 9+l; }
    }
    const int iw = 12, imask = 13;

    static int smem_set = 0;
    if (!smem_set) {
        cudaFuncSetAttribute(fused_kernel, cudaFuncAttributeMaxDynamicSharedMemorySize,
                             3 * kB * sizeof(unsigned int));
        smem_set = 1;
    }

    fused_kernel<<<kSegs, kT, 3 * kB * sizeof(unsigned int)>>>(
        (const float*)d_in[iopt[0]], (const float*)d_in[iopt[1]], (const float*)d_in[iopt[2]],
        (const float*)d_in[ihist[0]], (const float*)d_in[ihist[1]], (const float*)d_in[ihist[2]],
        (const float*)d_in[imin[0]], (const float*)d_in[imin[1]], (const float*)d_in[imin[2]],
        (const float*)d_in[imax[0]], (const float*)d_in[imax[1]], (const float*)d_in[imax[2]],
        (const int*)d_in[imask], (const float*)d_in[iw], (float*)d_out);
}